// round 10
// baseline (speedup 1.0000x reference)
#include <cuda_runtime.h>
#include <cstdint>

#define WARM_UP 365
#define NPHY    12
#define NMUL    4
#define LENF    15
#define MAX_T   2000
#define MAX_G   4000
#define CHUNK   40
#define GPB     32                 // grid cells per block
#define THREADS (GPB * 2)          // 64: each thread runs 2 chains (m-pair)

// Scratch (allocation-free per harness rules)
__device__ float g_qs4[(size_t)MAX_T * MAX_G * NMUL];  // [t][g*4+m]
__device__ float g_w[LENF * MAX_G];                    // [k][g]

__device__ __forceinline__ float fast_lg2(float x) {
    float r; asm("lg2.approx.f32 %0, %1;" : "=f"(r) : "f"(x)); return r;
}
__device__ __forceinline__ float fast_ex2(float x) {
    float r; asm("ex2.approx.f32 %0, %1;" : "=f"(r) : "f"(x)); return r;
}
__device__ __forceinline__ uint32_t smem_u32(const void* p) {
    return (uint32_t)__cvta_generic_to_shared(p);
}

// ---------------------------------------------------------------------------
// Kernel 1: HBV scan. Thread = (g, m-pair): runs 2 independent chains whose
// instruction streams interleave to fill dependency-stall slots.
// EXACT=true: G % GPB == 0 and T % CHUNK == 0 -> no per-iteration branches.
// ---------------------------------------------------------------------------
template <bool EXACT>
__global__ __launch_bounds__(THREADS)
void hbv_scan_kernel(const float* __restrict__ x_phy,
                     const float* __restrict__ params,
                     int T, int G)
{
    // +1 padding row so the steady-state prefetch of row i+1 never goes OOB
    __shared__ float sbufA[CHUNK + 1][GPB * 3];
    __shared__ float sbufB[CHUNK + 1][GPB * 3];

    const int tidx = threadIdx.x;
    const int gl   = tidx >> 1;           // local g (0..31)
    const int mp   = tidx & 1;            // m-pair: chains 2*mp, 2*mp+1
    const int g    = blockIdx.x * GPB + gl;
    const bool active = EXACT || (g < G);

    const float lb[NPHY] = {1.0f, 50.0f, 0.05f, 0.01f, 0.001f, 0.2f,
                            0.0f, 0.0f, -2.5f, 0.5f, 0.0f, 0.0f};
    const float ub[NPHY] = {6.0f, 1000.0f, 0.9f, 0.5f, 0.2f, 1.0f,
                            10.0f, 100.0f, 2.5f, 10.0f, 0.1f, 0.2f};

    // per-chain parameters
    float beta[2], fc[2], k0[2], k1[2], k2[2], lp[2];
    float perc[2], uzl[2], tt[2], cfmax[2], cfr[2], cwh[2];
#pragma unroll
    for (int c = 0; c < 2; c++) {
        float phy[NPHY];
#pragma unroll
        for (int i = 0; i < NPHY; i++) phy[i] = 0.5f;
        if (active) {
            const float* pp = params + (size_t)g * (NPHY * NMUL + 2);
#pragma unroll
            for (int i = 0; i < NPHY; i++)
                phy[i] = lb[i] + pp[i * NMUL + (2 * mp + c)] * (ub[i] - lb[i]);
        }
        beta[c] = phy[0]; fc[c] = phy[1]; k0[c] = phy[2];
        k1[c] = phy[3];   k2[c] = phy[4]; lp[c] = phy[5];
        perc[c] = phy[6]; uzl[c] = phy[7]; tt[c] = phy[8];
        cfmax[c] = phy[9]; cfr[c] = phy[10]; cwh[c] = phy[11];
    }

    float inv_lpfc[2], cfr_cfmax[2], blg_ifc[2];
#pragma unroll
    for (int c = 0; c < 2; c++) {
        inv_lpfc[c]  = 1.0f / (lp[c] * fc[c]);
        cfr_cfmax[c] = cfr[c] * cfmax[c];
        blg_ifc[c]   = beta[c] * fast_lg2(1.0f / fc[c]);
    }

    float snowpack[2] = {0.001f, 0.001f}, meltwater[2] = {0.001f, 0.001f};
    float sm[2] = {0.001f, 0.001f}, suz[2] = {0.001f, 0.001f};
    float slz[2] = {0.001f, 0.001f};

    const int row = G * 3;
    const float* gsrc = x_phy + (size_t)blockIdx.x * (GPB * 3);
    const int fbase = gl * 3;
    const int strideQ = G * NMUL;
    // thread writes chains 2mp, 2mp+1 -> adjacent floats, 8B-aligned
    float2* qout = (float2*)(g_qs4 + ((size_t)(g << 2) | (mp << 1)));
    const int strideQ2 = strideQ / 2;     // in float2 units

    auto issue_chunk = [&](float (*sb)[GPB * 3], int t0) {
        const int PK = GPB * 3 / 4;          // 16B packets per row (24)
        const int NV4 = CHUNK * PK;
#pragma unroll 4
        for (int idx = tidx; idx < NV4; idx += THREADS) {
            int i = idx / PK;
            int j = idx - i * PK;
            int t = t0 + i;
            if (!EXACT && t >= T) t = T - 1;
            const float* src = gsrc + (size_t)t * row + j * 4;
            uint32_t dst = smem_u32(&sb[i][j * 4]);
            asm volatile("cp.async.cg.shared.global [%0], [%1], 16;"
                         :: "r"(dst), "l"(src));
        }
        asm volatile("cp.async.commit_group;");
    };

    issue_chunk(sbufA, 0);
    asm volatile("cp.async.wait_group 0;");
    __syncthreads();

    // pipelined per-chain forcing-derived terms for the upcoming step
    float rain[2], snow[2], melt_cap[2], refr_cap[2], PE, om_pe[2];
    auto make_terms = [&](const float* f) {
        float P  = f[0];
        float Tt = f[1];
        PE       = f[2];
#pragma unroll
        for (int c = 0; c < 2; c++) {
            rain[c] = (Tt >= tt[c]) ? P : 0.0f;
            snow[c] = P - rain[c];
            melt_cap[c] = fmaxf(cfmax[c] * (Tt - tt[c]), 0.0f);
            refr_cap[c] = fmaxf(cfr_cfmax[c] * (tt[c] - Tt), 0.0f);
            om_pe[c] = 1.0f - PE * inv_lpfc[c];
        }
    };
    make_terms(&sbufA[0][fbase]);

    const int nchunks = (T + CHUNK - 1) / CHUNK;
    float (*cur)[GPB * 3] = sbufA;
    float (*nxt)[GPB * 3] = sbufB;

    for (int c0 = 0; c0 < nchunks; c0++) {
        const int t0 = c0 * CHUNK;
        const bool has_next = (c0 + 1 < nchunks);
        if (has_next)
            issue_chunk(nxt, t0 + CHUNK);

#pragma unroll 4
        for (int i = 0; i < CHUNK; i++) {
            float q[2];
#pragma unroll
            for (int c = 0; c < 2; c++) {
                // ---- soil wetness: MUFU pair off carried sm ----
                float sw = fast_ex2(fmaf(beta[c], fast_lg2(sm[c]), blg_ifc[c]));
                sw = fminf(sw, 1.0f);
                float oms = 1.0f - sw;

                // ---- snow module ----
                float sp1  = snowpack[c] + snow[c];
                float melt = fminf(melt_cap[c], sp1);
                float mw1  = meltwater[c] + melt;
                float sp2  = sp1 - melt;
                float refreeze = fminf(refr_cap[c], mw1);
                float sp3  = sp2 + refreeze;
                float mw2  = mw1 - refreeze;
                float thr  = cwh[c] * sp3;
                float tosoil = fmaxf(mw2 - thr, 0.0f);
                meltwater[c] = fminf(mw2, thr);
                snowpack[c]  = sp3;

                // ---- soil module ----
                float inflow   = rain[c] + tosoil;
                float recharge = inflow * sw;
                float sm2 = fmaf(inflow, oms, sm[c]);
                float sm3 = fminf(sm2, fc[c]);
                float excess = sm2 - sm3;
                sm[c] = fmaxf(fmaxf(sm3 * om_pe[c], sm3 - PE), 1e-5f);

                // ---- response routing ----
                float suz1 = suz[c] + recharge + excess;
                float suz2 = fmaxf(suz1 - perc[c], 0.0f);
                float prc  = suz1 - suz2;
                float q0   = k0[c] * fmaxf(suz2 - uzl[c], 0.0f);
                float suz3 = suz2 - q0;
                float q1   = k1[c] * suz3;
                suz[c] = suz3 - q1;
                float slz1 = slz[c] + prc;
                float q2   = k2[c] * slz1;
                slz[c] = slz1 - q2;

                q[c] = q0 + q1 + q2;
            }

            // ---- prefetch next step's forcing terms (off critical path) ----
            make_terms(&cur[i + 1][fbase]);

            // ---- paired coalesced store (STG.64, no branch in EXACT) ----
            if (EXACT) {
                *qout = make_float2(q[0], q[1]);
                qout += strideQ2;
            } else {
                int t = t0 + i;
                if (active && t < T)
                    qout[(size_t)(t - t0) * strideQ2] = make_float2(q[0], q[1]);
            }
        }
        if (!EXACT)
            qout += (size_t)CHUNK * strideQ2;

        if (has_next) {
            asm volatile("cp.async.wait_group 0;");
            __syncthreads();
            float (*tmp)[GPB * 3] = cur; cur = nxt; nxt = tmp;
            make_terms(&cur[0][fbase]);
        }
    }
}

// ---------------------------------------------------------------------------
// Kernel 2: normalized gamma routing weights (Γ(aa)·th^aa cancels).
// ---------------------------------------------------------------------------
__global__ __launch_bounds__(128)
void hbv_w_kernel(const float* __restrict__ params, int G)
{
    int g = blockIdx.x * blockDim.x + threadIdx.x;
    if (g >= G) return;
    const float* pp = params + (size_t)g * (NPHY * NMUL + 2);
    float a  = pp[NPHY * NMUL + 0] * 2.9f;
    float b  = pp[NPHY * NMUL + 1] * 6.5f;
    float aa = fmaxf(a, 0.0f) + 0.1f;
    float th = fmaxf(b, 0.0f) + 0.5f;
    float inv_th = 1.0f / th;

    float w[LENF];
    float s = 0.0f;
#pragma unroll
    for (int k = 0; k < LENF; k++) {
        float tg = (float)k + 0.5f;
        float v = expf((aa - 1.0f) * logf(tg) - tg * inv_th);
        w[k] = v;
        s += v;
    }
    float inv_s = 1.0f / s;
#pragma unroll
    for (int k = 0; k < LENF; k++)
        g_w[k * MAX_G + g] = w[k] * inv_s;
}

// ---------------------------------------------------------------------------
// Kernel 3: mean over NMUL (float4) + causal 15-tap conv; rolling window.
// ---------------------------------------------------------------------------
#define TS 16
__global__ __launch_bounds__(256)
void hbv_conv_kernel(float* __restrict__ out, int T, int G)
{
    int g = blockIdx.x * blockDim.x + threadIdx.x;
    if (g >= G) return;
    int t0 = WARM_UP + blockIdx.y * TS;

    const float4* q4 = (const float4*)g_qs4;   // index t*G + g

    float w[LENF];
#pragma unroll
    for (int k = 0; k < LENF; k++)
        w[k] = g_w[k * MAX_G + g];

    float qb[LENF - 1];
#pragma unroll
    for (int j = 0; j < LENF - 1; j++) {
        float4 v = q4[(size_t)(t0 - (LENF - 1) + j) * G + g];
        qb[j] = 0.25f * (v.x + v.y + v.z + v.w);
    }

#pragma unroll
    for (int i = 0; i < TS; i++) {
        int t = t0 + i;
        if (t >= T) break;
        float4 v = q4[(size_t)t * G + g];
        float qt = 0.25f * (v.x + v.y + v.z + v.w);
        float acc = qt * w[0];
#pragma unroll
        for (int k = 1; k < LENF; k++)
            acc += qb[LENF - 1 - k] * w[k];
#pragma unroll
        for (int j = 0; j < LENF - 2; j++)
            qb[j] = qb[j + 1];
        qb[LENF - 2] = qt;
        out[(size_t)(t - WARM_UP) * G + g] = acc;
    }
}

// ---------------------------------------------------------------------------
extern "C" void kernel_launch(void* const* d_in, const int* in_sizes, int n_in,
                              void* d_out, int out_size)
{
    int ix = 0, ip = 1;
    if (in_sizes[0] < in_sizes[1]) { ix = 1; ip = 0; }
    const float* x_phy  = (const float*)d_in[ix];
    const float* params = (const float*)d_in[ip];
    float* out = (float*)d_out;

    int G = in_sizes[ip] / (NPHY * NMUL + 2);
    int T = in_sizes[ix] / (3 * G);

    int nblk = (G + GPB - 1) / GPB;
    if ((G % GPB) == 0 && (T % CHUNK) == 0)
        hbv_scan_kernel<true><<<nblk, THREADS>>>(x_phy, params, T, G);
    else
        hbv_scan_kernel<false><<<nblk, THREADS>>>(x_phy, params, T, G);

    hbv_w_kernel<<<(G + 127) / 128, 128>>>(params, G);
    dim3 gconv((G + 255) / 256, (T - WARM_UP + TS - 1) / TS);
    hbv_conv_kernel<<<gconv, 256>>>(out, T, G);
}